// round 15
// baseline (speedup 1.0000x reference)
#include <cuda_runtime.h>
#include <cuda_fp16.h>

typedef unsigned int u32;

#define PPB 8
#define NT  128

#define ROWB   80
#define B_TAP  2560
#define OFF_BIAS0 0
#define OFF_BIAS1 128
#define OFF_COL   256
#define OFF_AH    1024
#define OFF_AL    (OFF_AH + 32000)
#define OFF_BH    (OFF_AL + 32000)
#define OFF_BL    (OFF_BH + 23040)
#define SMEM_TOTAL (OFF_BL + 23040)    // 111104 B

__device__ __forceinline__ u32 smem_u32(const void* p){
    u32 a; asm("{ .reg .u64 t; cvta.to.shared.u64 t, %1; cvt.u32.u64 %0, t; }":"=r"(a):"l"(p)); return a;
}
__device__ __forceinline__ void ldsm4(u32 a, u32* r){
    asm volatile("ldmatrix.sync.aligned.m8n8.x4.shared.b16 {%0,%1,%2,%3},[%4];"
        : "=r"(r[0]),"=r"(r[1]),"=r"(r[2]),"=r"(r[3]) : "r"(a));
}
__device__ __forceinline__ void hmma(float* d, const u32* a, const u32* b){
    asm volatile("mma.sync.aligned.m16n8k16.row.col.f32.f16.f16.f32 "
        "{%0,%1,%2,%3},{%4,%5,%6,%7},{%8,%9},{%0,%1,%2,%3};"
        : "+f"(d[0]),"+f"(d[1]),"+f"(d[2]),"+f"(d[3])
        : "r"(a[0]),"r"(a[1]),"r"(a[2]),"r"(a[3]),"r"(b[0]),"r"(b[1]));
}
__device__ __forceinline__ u32 packh(__half a, __half b){
    return (u32)__half_as_ushort(a) | ((u32)__half_as_ushort(b) << 16);
}
__device__ __forceinline__ void split2(float v, __half& h, __half& l){
    h = __float2half_rn(v);
    l = __float2half_rn(v - __half2float(h));
}

// One layer's MMA. 4 warps; warp owns up to 4 M-tiles (arbitrary slot pairs).
// Loop: tap -> k -> {B loaded once} -> 4 M-tiles, splits ordered nt-inner.
template<int KT, int NTL>
__device__ __forceinline__ void layer_mma(u32 sb, int lane,
                                          const u32 abase[4], const bool val[4],
                                          float d[4][4][4])
{
    #pragma unroll
    for (int mt = 0; mt < 4; mt++)
        #pragma unroll
        for (int nt = 0; nt < 4; nt++)
            #pragma unroll
            for (int q = 0; q < 4; q++) d[mt][nt][q] = 0.f;

    const int bn  = (lane & 7) + ((lane >> 4) << 3);
    const u32 bko = (u32)(((lane >> 3) & 1) * 16);
    const u32 bbase = (u32)(bn * ROWB) + bko;

    #pragma unroll 1
    for (int tap = 0; tap < 9; tap++) {
        const int dmB = (((tap / 3) * 7 + (tap % 3)) - 8) * 8 * ROWB;
        #pragma unroll
        for (int k = 0; k < KT; k++) {
            const u32 boff = (u32)(tap * B_TAP + k * 32) + bbase;
            u32 bh0[4], bl0[4], bh1[4], bl1[4];
            ldsm4(sb + OFF_BH + boff, bh0);
            ldsm4(sb + OFF_BL + boff, bl0);
            if (NTL > 2) {
                ldsm4(sb + OFF_BH + boff + 1280, bh1);
                ldsm4(sb + OFF_BL + boff + 1280, bl1);
            }
            #pragma unroll
            for (int mt = 0; mt < 4; mt++) {
                if (!val[mt]) continue;
                const u32 aoff = abase[mt] + (u32)(dmB + k * 32);
                u32 ah[4], al[4];
                ldsm4(sb + OFF_AH + aoff, ah);
                ldsm4(sb + OFF_AL + aoff, al);
                // hh
                hmma(d[mt][0], ah, bh0 + 0);
                if (NTL > 1) hmma(d[mt][1], ah, bh0 + 2);
                if (NTL > 2) { hmma(d[mt][2], ah, bh1 + 0); hmma(d[mt][3], ah, bh1 + 2); }
                // hl
                hmma(d[mt][0], ah, bl0 + 0);
                if (NTL > 1) hmma(d[mt][1], ah, bl0 + 2);
                if (NTL > 2) { hmma(d[mt][2], ah, bl1 + 0); hmma(d[mt][3], ah, bl1 + 2); }
                // lh
                hmma(d[mt][0], al, bh0 + 0);
                if (NTL > 1) hmma(d[mt][1], al, bh0 + 2);
                if (NTL > 2) { hmma(d[mt][2], al, bh1 + 0); hmma(d[mt][3], al, bh1 + 2); }
            }
        }
    }
}

__global__ __launch_bounds__(NT, 2)
void Kpcnn_49160195670356_kernel(const float* __restrict__ gin,
                                 const float* __restrict__ w0,
                                 const float* __restrict__ b0,
                                 const float* __restrict__ wmid,
                                 const float* __restrict__ bmid,
                                 const float* __restrict__ wlast,
                                 const float* __restrict__ blast,
                                 const float* __restrict__ wpost,
                                 const float* __restrict__ bpost,
                                 float* __restrict__ gout)
{
    extern __shared__ char smem[];
    const u32 sb  = smem_u32(smem);
    const int tid = threadIdx.x;
    const int wid = tid >> 5;
    const int lane = tid & 31;
    const long pg = (long)blockIdx.x * PPB;

    float* bias0  = (float*)(smem + OFF_BIAS0);
    float* bias1  = (float*)(smem + OFF_BIAS1);
    float* colors = (float*)(smem + OFF_COL);

    // per-warp tile setup: tile = wid + 4*mt; slots paired arbitrarily (13 tiles)
    u32 abase[4]; bool val[4]; int sA[4], sB[4], tdup[4];
    #pragma unroll
    for (int mt = 0; mt < 4; mt++) {
        const int tile = wid + mt * 4;
        val[mt] = (tile < 13);
        const int i2 = val[mt] ? 2 * tile : 0;
        const int a_ = (i2 / 5) * 7 + (i2 % 5) + 8;
        const int i3 = (i2 + 1 <= 24) ? (i2 + 1) : 0;
        const int b_ = (i3 / 5) * 7 + (i3 % 5) + 8;
        sA[mt] = a_; sB[mt] = b_;
        tdup[mt] = (i2 + 1 > 24);            // tile 12: slotB is dup, don't write
        const int ssel = ((lane >> 3) & 1) ? b_ : a_;
        abase[mt] = (u32)((ssel * 8 + (lane & 7)) * ROWB + ((lane >> 4) * 16));
    }

    // ---- zero A + B (both splits) ----
    {
        uint4 z = make_uint4(0, 0, 0, 0);
        uint4* p4 = (uint4*)(smem + OFF_AH);
        for (int i = tid; i < (SMEM_TOTAL - OFF_AH) / 16; i += NT) p4[i] = z;
    }
    __syncthreads();

    // ---- stage input, conv0 weights, bias0, colors ----
    for (int i = tid; i < PPB * 200; i += NT) {
        const int p = i / 200, rem = i % 200;
        const int c = rem / 25, pos = rem % 25;
        const int slot = (pos / 5 + 1) * 7 + (pos % 5 + 1);
        const int row = slot * 8 + p;
        const float v = gin[(pg + p) * 200 + rem];
        __half h, l; split2(v, h, l);
        *(__half*)(smem + OFF_AH + row * ROWB + c * 2) = h;
        *(__half*)(smem + OFF_AL + row * ROWB + c * 2) = l;
    }
    for (int i = tid; i < 25 * 72; i += NT) {
        const int oc = i / 72, r = i % 72, ic = r / 9, tap = r % 9;
        __half h, l; split2(w0[i], h, l);
        const int off = tap * B_TAP + oc * ROWB + ic * 2;
        *(__half*)(smem + OFF_BH + off) = h;
        *(__half*)(smem + OFF_BL + off) = l;
    }
    if (tid < 32) bias0[tid] = (tid < 25) ? b0[tid] : 0.f;
    for (int t = tid; t < 144; t += NT) {
        const int p = t / 18, j = t % 18;
        const float* wp = wpost + j * 75;
        const float* ip = gin + (pg + p) * 200;
        float a0 = bpost[j], a1 = 0.f, a2 = 0.f;
        #pragma unroll
        for (int k = 0; k < 25; k++) {
            a0 = fmaf(wp[k],      ip[k],      a0);
            a1 = fmaf(wp[25 + k], ip[25 + k], a1);
            a2 = fmaf(wp[50 + k], ip[50 + k], a2);
        }
        colors[p * 18 + j] = a0 + a1 + a2;
    }
    __syncthreads();

    float d[4][4][4];

    // ---- conv0 (K=16, ic 8..15 zero) ----
    layer_mma<1, 4>(sb, lane, abase, val, d);
    __syncthreads();

    // epilogue helper (inlined twice below as lambda-style macro)
    #define EPI_CONV(BIAS) do {                                                   \
        _Pragma("unroll")                                                         \
        for (int mt = 0; mt < 4; mt++) {                                          \
            if (!val[mt]) continue;                                               \
            const int rA = sA[mt] * 8 + (lane >> 2);                              \
            const int rB = sB[mt] * 8 + (lane >> 2);                              \
            _Pragma("unroll")                                                     \
            for (int nt = 0; nt < 4; nt++) {                                      \
                const int col = nt * 8 + (lane & 3) * 2;                          \
                const float b0v = (BIAS)[col], b1v = (BIAS)[col + 1];             \
                float v0 = fmaxf(d[mt][nt][0] + b0v, 0.f);                        \
                float v1 = fmaxf(d[mt][nt][1] + b1v, 0.f);                        \
                __half h0, l0, h1, l1;                                            \
                split2(v0, h0, l0); split2(v1, h1, l1);                           \
                *(u32*)(smem + OFF_AH + rA * ROWB + col * 2) = packh(h0, h1);     \
                *(u32*)(smem + OFF_AL + rA * ROWB + col * 2) = packh(l0, l1);     \
                if (!tdup[mt]) {                                                  \
                    float v2 = fmaxf(d[mt][nt][2] + b0v, 0.f);                    \
                    float v3 = fmaxf(d[mt][nt][3] + b1v, 0.f);                    \
                    __half h2, l2, h3, l3;                                        \
                    split2(v2, h2, l2); split2(v3, h3, l3);                       \
                    *(u32*)(smem + OFF_AH + rB * ROWB + col * 2) = packh(h2, h3); \
                    *(u32*)(smem + OFF_AL + rB * ROWB + col * 2) = packh(l2, l3); \
                }                                                                 \
            }                                                                     \
        }                                                                         \
    } while (0)

    EPI_CONV(bias0);
    for (int i = tid; i < 5625; i += NT) {
        const int oc = i / 225, r = i % 225, ic = r / 9, tap = r % 9;
        __half h, l; split2(wmid[i], h, l);
        const int off = tap * B_TAP + oc * ROWB + ic * 2;
        *(__half*)(smem + OFF_BH + off) = h;
        *(__half*)(smem + OFF_BL + off) = l;
    }
    if (tid < 32) bias1[tid] = (tid < 25) ? bmid[tid] : 0.f;
    __syncthreads();

    // ---- 6 mid layers ----
    #pragma unroll 1
    for (int L = 0; L < 6; L++) {
        layer_mma<2, 4>(sb, lane, abase, val, d);
        __syncthreads();
        const float* rb = (L & 1) ? bias0 : bias1;
        float* wb = (L & 1) ? bias1 : bias0;
        EPI_CONV(rb);
        if (L < 5) {
            const float* wsrc = wmid + (long)(L + 1) * 5625;
            for (int i = tid; i < 5625; i += NT) {
                const int oc = i / 225, r = i % 225, ic = r / 9, tap = r % 9;
                __half h, l; split2(wsrc[i], h, l);
                const int off = tap * B_TAP + oc * ROWB + ic * 2;
                *(__half*)(smem + OFF_BH + off) = h;
                *(__half*)(smem + OFF_BL + off) = l;
            }
            if (tid < 32) wb[tid] = (tid < 25) ? bmid[(L + 1) * 25 + tid] : 0.f;
        } else {
            for (int i = tid; i < 9 * 8 * 32; i += NT) {
                const int tap = i / 256, r2 = i % 256, oc = r2 / 32, ic = r2 % 32;
                const float v = (oc < 6 && ic < 25) ? wlast[oc * 225 + ic * 9 + tap] : 0.f;
                __half h, l; split2(v, h, l);
                const int off = tap * B_TAP + oc * ROWB + ic * 2;
                *(__half*)(smem + OFF_BH + off) = h;
                *(__half*)(smem + OFF_BL + off) = l;
            }
            if (tid < 8) wb[tid] = (tid < 6) ? blast[tid] : -1e30f;
        }
        __syncthreads();
    }

    // ---- last conv (N=8: 6 logits) + softmax + einsum ----
    layer_mma<2, 1>(sb, lane, abase, val, d);
    __syncthreads();
    const float* lb = bias1;
    #pragma unroll
    for (int mt = 0; mt < 4; mt++) {
        if (!val[mt]) continue;
        const int patch = lane >> 2;
        const int w0i = (lane & 3) * 2;
        const float bw0 = lb[w0i], bw1 = lb[w0i + 1];
        #pragma unroll
        for (int half = 0; half < 2; half++) {
            if (half == 1 && tdup[mt]) continue;       // warp-uniform skip
            const float lg0 = d[mt][0][half * 2 + 0] + bw0;
            const float lg1 = d[mt][0][half * 2 + 1] + bw1;
            float mx = fmaxf(lg0, lg1);
            mx = fmaxf(mx, __shfl_xor_sync(0xffffffffu, mx, 1));
            mx = fmaxf(mx, __shfl_xor_sync(0xffffffffu, mx, 2));
            const float e0 = __expf(lg0 - mx);
            const float e1 = __expf(lg1 - mx);
            float sm = e0 + e1;
            sm += __shfl_xor_sync(0xffffffffu, sm, 1);
            sm += __shfl_xor_sync(0xffffffffu, sm, 2);
            const float inv = 1.0f / sm;
            float p0 = 0.f, p1 = 0.f, p2 = 0.f;
            if ((lane & 3) != 3) {
                const float* cl = colors + patch * 18;
                p0 = cl[w0i] * e0      + cl[w0i + 1] * e1;
                p1 = cl[6 + w0i] * e0  + cl[7 + w0i] * e1;
                p2 = cl[12 + w0i] * e0 + cl[13 + w0i] * e1;
            }
            p0 += __shfl_xor_sync(0xffffffffu, p0, 1);
            p0 += __shfl_xor_sync(0xffffffffu, p0, 2);
            p1 += __shfl_xor_sync(0xffffffffu, p1, 1);
            p1 += __shfl_xor_sync(0xffffffffu, p1, 2);
            p2 += __shfl_xor_sync(0xffffffffu, p2, 1);
            p2 += __shfl_xor_sync(0xffffffffu, p2, 2);
            if ((lane & 3) == 0) {
                const int s = half ? sB[mt] : sA[mt];
                const int y = s / 7, x = s % 7;
                const long ob = (pg + patch) * 75 + (y - 1) * 5 + (x - 1);
                gout[ob]      = p0 * inv;
                gout[ob + 25] = p1 * inv;
                gout[ob + 50] = p2 * inv;
            }
        }
    }
}

extern "C" void kernel_launch(void* const* d_in, const int* in_sizes, int n_in,
                              void* d_out, int out_size)
{
    const float* gin   = (const float*)d_in[0];
    const float* w0    = (const float*)d_in[1];
    const float* b0    = (const float*)d_in[2];
    const float* wmid  = (const float*)d_in[3];
    const float* bmid  = (const float*)d_in[4];
    const float* wlast = (const float*)d_in[5];
    const float* blast = (const float*)d_in[6];
    const float* wpost = (const float*)d_in[7];
    const float* bpost = (const float*)d_in[8];
    float* gout = (float*)d_out;

    cudaFuncSetAttribute(Kpcnn_49160195670356_kernel,
                         cudaFuncAttributeMaxDynamicSharedMemorySize, SMEM_TOTAL);

    Kpcnn_49160195670356_kernel<<<32768 / PPB, NT, SMEM_TOTAL>>>(
        gin, w0, b0, wmid, bmid, wlast, blast, wpost, bpost, gout);
}

// round 16
// speedup vs baseline: 1.2136x; 1.2136x over previous
#include <cuda_runtime.h>
#include <cuda_fp16.h>

typedef unsigned int u32;

#define PPB 8
#define NT  256

#define ROWB   80
#define B_TAP  2560
#define OFF_BIAS0 0
#define OFF_BIAS1 128
#define OFF_COL   256
#define OFF_AH    1024
#define OFF_AL    (OFF_AH + 32000)
#define OFF_BH    (OFF_AL + 32000)
#define OFF_BL    (OFF_BH + 23040)
#define SMEM_TOTAL (OFF_BL + 23040)    // 111104 B

__device__ __forceinline__ u32 smem_u32(const void* p){
    u32 a; asm("{ .reg .u64 t; cvta.to.shared.u64 t, %1; cvt.u32.u64 %0, t; }":"=r"(a):"l"(p)); return a;
}
__device__ __forceinline__ void ldsm4(u32 a, u32* r){
    asm volatile("ldmatrix.sync.aligned.m8n8.x4.shared.b16 {%0,%1,%2,%3},[%4];"
        : "=r"(r[0]),"=r"(r[1]),"=r"(r[2]),"=r"(r[3]) : "r"(a));
}
__device__ __forceinline__ void hmma(float* d, const u32* a, const u32* b){
    asm volatile("mma.sync.aligned.m16n8k16.row.col.f32.f16.f16.f32 "
        "{%0,%1,%2,%3},{%4,%5,%6,%7},{%8,%9},{%0,%1,%2,%3};"
        : "+f"(d[0]),"+f"(d[1]),"+f"(d[2]),"+f"(d[3])
        : "r"(a[0]),"r"(a[1]),"r"(a[2]),"r"(a[3]),"r"(b[0]),"r"(b[1]));
}
__device__ __forceinline__ u32 packh(__half a, __half b){
    return (u32)__half_as_ushort(a) | ((u32)__half_as_ushort(b) << 16);
}
__device__ __forceinline__ void split2(float v, __half& h, __half& l){
    h = __float2half_rn(v);
    l = __float2half_rn(v - __half2float(h));
}

// One layer's MMA. 8 warps; warp owns up to 2 M-tiles (tile = wid + 8*mt).
template<int KT, int NTL>
__device__ __forceinline__ void layer_mma(u32 sb, int lane,
                                          const u32 abase[2], const bool val[2],
                                          float d[2][4][4])
{
    #pragma unroll
    for (int mt = 0; mt < 2; mt++)
        #pragma unroll
        for (int nt = 0; nt < 4; nt++)
            #pragma unroll
            for (int q = 0; q < 4; q++) d[mt][nt][q] = 0.f;

    const int bn  = (lane & 7) + ((lane >> 4) << 3);
    const u32 bko = (u32)(((lane >> 3) & 1) * 16);
    const u32 bbase = (u32)(bn * ROWB) + bko;

    #pragma unroll 1
    for (int tap = 0; tap < 9; tap++) {
        const int dmB = (((tap / 3) * 7 + (tap % 3)) - 8) * 8 * ROWB;
        #pragma unroll
        for (int k = 0; k < KT; k++) {
            const u32 boff = (u32)(tap * B_TAP + k * 32) + bbase;
            u32 bh0[4], bl0[4], bh1[4], bl1[4];
            ldsm4(sb + OFF_BH + boff, bh0);
            ldsm4(sb + OFF_BL + boff, bl0);
            if (NTL > 2) {
                ldsm4(sb + OFF_BH + boff + 1280, bh1);
                ldsm4(sb + OFF_BL + boff + 1280, bl1);
            }
            #pragma unroll
            for (int mt = 0; mt < 2; mt++) {
                if (!val[mt]) continue;
                const u32 aoff = abase[mt] + (u32)(dmB + k * 32);
                u32 ah[4], al[4];
                ldsm4(sb + OFF_AH + aoff, ah);
                ldsm4(sb + OFF_AL + aoff, al);
                hmma(d[mt][0], ah, bh0 + 0);
                if (NTL > 1) hmma(d[mt][1], ah, bh0 + 2);
                if (NTL > 2) { hmma(d[mt][2], ah, bh1 + 0); hmma(d[mt][3], ah, bh1 + 2); }
                hmma(d[mt][0], ah, bl0 + 0);
                if (NTL > 1) hmma(d[mt][1], ah, bl0 + 2);
                if (NTL > 2) { hmma(d[mt][2], ah, bl1 + 0); hmma(d[mt][3], ah, bl1 + 2); }
                hmma(d[mt][0], al, bh0 + 0);
                if (NTL > 1) hmma(d[mt][1], al, bh0 + 2);
                if (NTL > 2) { hmma(d[mt][2], al, bh1 + 0); hmma(d[mt][3], al, bh1 + 2); }
            }
        }
    }
}

__global__ __launch_bounds__(NT, 2)
void Kpcnn_49160195670356_kernel(const float* __restrict__ gin,
                                 const float* __restrict__ w0,
                                 const float* __restrict__ b0,
                                 const float* __restrict__ wmid,
                                 const float* __restrict__ bmid,
                                 const float* __restrict__ wlast,
                                 const float* __restrict__ blast,
                                 const float* __restrict__ wpost,
                                 const float* __restrict__ bpost,
                                 float* __restrict__ gout)
{
    extern __shared__ char smem[];
    const u32 sb  = smem_u32(smem);
    const int tid = threadIdx.x;
    const int wid = tid >> 5;
    const int lane = tid & 31;
    const long pg = (long)blockIdx.x * PPB;

    float* bias0  = (float*)(smem + OFF_BIAS0);
    float* bias1  = (float*)(smem + OFF_BIAS1);
    float* colors = (float*)(smem + OFF_COL);

    // per-warp tiles: tile = wid + 8*mt, 13 tiles total (paired slots)
    u32 abase[2]; bool val[2]; int sA[2], sB[2], tdup[2];
    #pragma unroll
    for (int mt = 0; mt < 2; mt++) {
        const int tile = wid + mt * 8;
        val[mt] = (tile < 13);
        const int i2 = val[mt] ? 2 * tile : 0;
        const int a_ = (i2 / 5) * 7 + (i2 % 5) + 8;
        const int i3 = (i2 + 1 <= 24) ? (i2 + 1) : 0;
        const int b_ = (i3 / 5) * 7 + (i3 % 5) + 8;
        sA[mt] = a_; sB[mt] = b_;
        tdup[mt] = (i2 + 1 > 24);
        const int ssel = ((lane >> 3) & 1) ? b_ : a_;
        abase[mt] = (u32)((ssel * 8 + (lane & 7)) * ROWB + ((lane >> 4) * 16));
    }

    // ---- zero A + B (both splits) ----
    {
        uint4 z = make_uint4(0, 0, 0, 0);
        uint4* p4 = (uint4*)(smem + OFF_AH);
        for (int i = tid; i < (SMEM_TOTAL - OFF_AH) / 16; i += NT) p4[i] = z;
    }
    __syncthreads();

    // ---- stage input, conv0 weights, bias0, colors ----
    for (int i = tid; i < PPB * 200; i += NT) {
        const int p = i / 200, rem = i % 200;
        const int c = rem / 25, pos = rem % 25;
        const int slot = (pos / 5 + 1) * 7 + (pos % 5 + 1);
        const int row = slot * 8 + p;
        const float v = gin[(pg + p) * 200 + rem];
        __half h, l; split2(v, h, l);
        *(__half*)(smem + OFF_AH + row * ROWB + c * 2) = h;
        *(__half*)(smem + OFF_AL + row * ROWB + c * 2) = l;
    }
    for (int i = tid; i < 25 * 72; i += NT) {
        const int oc = i / 72, r = i % 72, ic = r / 9, tap = r % 9;
        __half h, l; split2(w0[i], h, l);
        const int off = tap * B_TAP + oc * ROWB + ic * 2;
        *(__half*)(smem + OFF_BH + off) = h;
        *(__half*)(smem + OFF_BL + off) = l;
    }
    if (tid < 32) bias0[tid] = (tid < 25) ? b0[tid] : 0.f;
    if (tid < 144) {
        const int p = tid / 18, j = tid % 18;
        const float* wp = wpost + j * 75;
        const float* ip = gin + (pg + p) * 200;
        float a0 = bpost[j], a1 = 0.f, a2 = 0.f;
        #pragma unroll
        for (int k = 0; k < 25; k++) {
            a0 = fmaf(wp[k],      ip[k],      a0);
            a1 = fmaf(wp[25 + k], ip[25 + k], a1);
            a2 = fmaf(wp[50 + k], ip[50 + k], a2);
        }
        colors[p * 18 + j] = a0 + a1 + a2;
    }
    __syncthreads();

    float d[2][4][4];

    // ---- conv0 (K=16, ic 8..15 zero) ----
    layer_mma<1, 4>(sb, lane, abase, val, d);
    __syncthreads();

    #define EPI_CONV(BIAS) do {                                                   \
        _Pragma("unroll")                                                         \
        for (int mt = 0; mt < 2; mt++) {                                          \
            if (!val[mt]) continue;                                               \
            const int rA = sA[mt] * 8 + (lane >> 2);                              \
            const int rB = sB[mt] * 8 + (lane >> 2);                              \
            _Pragma("unroll")                                                     \
            for (int nt = 0; nt < 4; nt++) {                                      \
                const int col = nt * 8 + (lane & 3) * 2;                          \
                const float b0v = (BIAS)[col], b1v = (BIAS)[col + 1];             \
                float v0 = fmaxf(d[mt][nt][0] + b0v, 0.f);                        \
                float v1 = fmaxf(d[mt][nt][1] + b1v, 0.f);                        \
                __half h0, l0, h1, l1;                                            \
                split2(v0, h0, l0); split2(v1, h1, l1);                           \
                *(u32*)(smem + OFF_AH + rA * ROWB + col * 2) = packh(h0, h1);     \
                *(u32*)(smem + OFF_AL + rA * ROWB + col * 2) = packh(l0, l1);     \
                if (!tdup[mt]) {                                                  \
                    float v2 = fmaxf(d[mt][nt][2] + b0v, 0.f);                    \
                    float v3 = fmaxf(d[mt][nt][3] + b1v, 0.f);                    \
                    __half h2, l2, h3, l3;                                        \
                    split2(v2, h2, l2); split2(v3, h3, l3);                       \
                    *(u32*)(smem + OFF_AH + rB * ROWB + col * 2) = packh(h2, h3); \
                    *(u32*)(smem + OFF_AL + rB * ROWB + col * 2) = packh(l2, l3); \
                }                                                                 \
            }                                                                     \
        }                                                                         \
    } while (0)

    EPI_CONV(bias0);
    for (int i = tid; i < 5625; i += NT) {
        const int oc = i / 225, r = i % 225, ic = r / 9, tap = r % 9;
        __half h, l; split2(wmid[i], h, l);
        const int off = tap * B_TAP + oc * ROWB + ic * 2;
        *(__half*)(smem + OFF_BH + off) = h;
        *(__half*)(smem + OFF_BL + off) = l;
    }
    if (tid < 32) bias1[tid] = (tid < 25) ? bmid[tid] : 0.f;
    __syncthreads();

    // ---- 6 mid layers ----
    #pragma unroll 1
    for (int L = 0; L < 6; L++) {
        layer_mma<2, 4>(sb, lane, abase, val, d);
        __syncthreads();
        const float* rb = (L & 1) ? bias0 : bias1;
        float* wb = (L & 1) ? bias1 : bias0;
        EPI_CONV(rb);
        if (L < 5) {
            const float* wsrc = wmid + (long)(L + 1) * 5625;
            for (int i = tid; i < 5625; i += NT) {
                const int oc = i / 225, r = i % 225, ic = r / 9, tap = r % 9;
                __half h, l; split2(wsrc[i], h, l);
                const int off = tap * B_TAP + oc * ROWB + ic * 2;
                *(__half*)(smem + OFF_BH + off) = h;
                *(__half*)(smem + OFF_BL + off) = l;
            }
            if (tid < 32) wb[tid] = (tid < 25) ? bmid[(L + 1) * 25 + tid] : 0.f;
        } else {
            for (int i = tid; i < 9 * 8 * 32; i += NT) {
                const int tap = i / 256, r2 = i % 256, oc = r2 / 32, ic = r2 % 32;
                const float v = (oc < 6 && ic < 25) ? wlast[oc * 225 + ic * 9 + tap] : 0.f;
                __half h, l; split2(v, h, l);
                const int off = tap * B_TAP + oc * ROWB + ic * 2;
                *(__half*)(smem + OFF_BH + off) = h;
                *(__half*)(smem + OFF_BL + off) = l;
            }
            if (tid < 8) wb[tid] = (tid < 6) ? blast[tid] : -1e30f;
        }
        __syncthreads();
    }

    // ---- last conv (N=8: 6 logits) + softmax + einsum ----
    layer_mma<2, 1>(sb, lane, abase, val, d);
    __syncthreads();
    const float* lb = bias1;
    #pragma unroll
    for (int mt = 0; mt < 2; mt++) {
        if (!val[mt]) continue;
        const int patch = lane >> 2;
        const int w0i = (lane & 3) * 2;
        const float bw0 = lb[w0i], bw1 = lb[w0i + 1];
        #pragma unroll
        for (int half = 0; half < 2; half++) {
            if (half == 1 && tdup[mt]) continue;
            const float lg0 = d[mt][0][half * 2 + 0] + bw0;
            const float lg1 = d[mt][0][half * 2 + 1] + bw1;
            float mx = fmaxf(lg0, lg1);
            mx = fmaxf(mx, __shfl_xor_sync(0xffffffffu, mx, 1));
            mx = fmaxf(mx, __shfl_xor_sync(0xffffffffu, mx, 2));
            const float e0 = __expf(lg0 - mx);
            const float e1 = __expf(lg1 - mx);
            float sm = e0 + e1;
            sm += __shfl_xor_sync(0xffffffffu, sm, 1);
            sm += __shfl_xor_sync(0xffffffffu, sm, 2);
            const float inv = 1.0f / sm;
            float p0 = 0.f, p1 = 0.f, p2 = 0.f;
            if ((lane & 3) != 3) {
                const float* cl = colors + patch * 18;
                p0 = cl[w0i] * e0      + cl[w0i + 1] * e1;
                p1 = cl[6 + w0i] * e0  + cl[7 + w0i] * e1;
                p2 = cl[12 + w0i] * e0 + cl[13 + w0i] * e1;
            }
            p0 += __shfl_xor_sync(0xffffffffu, p0, 1);
            p0 += __shfl_xor_sync(0xffffffffu, p0, 2);
            p1 += __shfl_xor_sync(0xffffffffu, p1, 1);
            p1 += __shfl_xor_sync(0xffffffffu, p1, 2);
            p2 += __shfl_xor_sync(0xffffffffu, p2, 1);
            p2 += __shfl_xor_sync(0xffffffffu, p2, 2);
            if ((lane & 3) == 0) {
                const int s = half ? sB[mt] : sA[mt];
                const int y = s / 7, x = s % 7;
                const long ob = (pg + patch) * 75 + (y - 1) * 5 + (x - 1);
                gout[ob]      = p0 * inv;
                gout[ob + 25] = p1 * inv;
                gout[ob + 50] = p2 * inv;
            }
        }
    }
}

extern "C" void kernel_launch(void* const* d_in, const int* in_sizes, int n_in,
                              void* d_out, int out_size)
{
    const float* gin   = (const float*)d_in[0];
    const float* w0    = (const float*)d_in[1];
    const float* b0    = (const float*)d_in[2];
    const float* wmid  = (const float*)d_in[3];
    const float* bmid  = (const float*)d_in[4];
    const float* wlast = (const float*)d_in[5];
    const float* blast = (const float*)d_in[6];
    const float* wpost = (const float*)d_in[7];
    const float* bpost = (const float*)d_in[8];
    float* gout = (float*)d_out;

    cudaFuncSetAttribute(Kpcnn_49160195670356_kernel,
                         cudaFuncAttributeMaxDynamicSharedMemorySize, SMEM_TOTAL);

    Kpcnn_49160195670356_kernel<<<32768 / PPB, NT, SMEM_TOTAL>>>(
        gin, w0, b0, wmid, bmid, wlast, blast, wpost, bpost, gout);
}

// round 17
// speedup vs baseline: 1.4361x; 1.1833x over previous
#include <cuda_runtime.h>
#include <cuda_fp16.h>

typedef unsigned int u32;

#define PPB 8
#define NT  256

#define ROWB   80
#define B_TAP  2560
#define WIMG_HALF  23040                // one split (9 taps * 32 rows * 80 B)
#define WIMG_BYTES 46080                // hi + lo
#define OFF_BIAS0 0
#define OFF_BIAS1 128
#define OFF_COL   256
#define OFF_AH    1024
#define OFF_AL    (OFF_AH + 32000)
#define OFF_BH    (OFF_AL + 32000)
#define OFF_BL    (OFF_BH + WIMG_HALF)
#define SMEM_TOTAL (OFF_BL + WIMG_HALF)    // 111104 B

// Precomputed split-weight smem images: [0]=conv0, [1..6]=mid, [7]=last
__device__ __align__(16) unsigned char g_wimg[8][WIMG_BYTES];

__device__ __forceinline__ u32 smem_u32(const void* p){
    u32 a; asm("{ .reg .u64 t; cvta.to.shared.u64 t, %1; cvt.u32.u64 %0, t; }":"=r"(a):"l"(p)); return a;
}
__device__ __forceinline__ void ldsm4(u32 a, u32* r){
    asm volatile("ldmatrix.sync.aligned.m8n8.x4.shared.b16 {%0,%1,%2,%3},[%4];"
        : "=r"(r[0]),"=r"(r[1]),"=r"(r[2]),"=r"(r[3]) : "r"(a));
}
__device__ __forceinline__ void hmma(float* d, const u32* a, const u32* b){
    asm volatile("mma.sync.aligned.m16n8k16.row.col.f32.f16.f16.f32 "
        "{%0,%1,%2,%3},{%4,%5,%6,%7},{%8,%9},{%0,%1,%2,%3};"
        : "+f"(d[0]),"+f"(d[1]),"+f"(d[2]),"+f"(d[3])
        : "r"(a[0]),"r"(a[1]),"r"(a[2]),"r"(a[3]),"r"(b[0]),"r"(b[1]));
}
__device__ __forceinline__ u32 packh(__half a, __half b){
    return (u32)__half_as_ushort(a) | ((u32)__half_as_ushort(b) << 16);
}
__device__ __forceinline__ void split2(float v, __half& h, __half& l){
    h = __float2half_rn(v);
    l = __float2half_rn(v - __half2float(h));
}

// ---- prep kernels (run before main; graph-capturable) ----
__global__ void Kprep_zero(){
    uint4* p = (uint4*)g_wimg;
    const int n = sizeof(g_wimg) / 16;
    for (int i = blockIdx.x * blockDim.x + threadIdx.x; i < n; i += gridDim.x * blockDim.x)
        p[i] = make_uint4(0, 0, 0, 0);
}
__global__ void Kprep_fill(const float* __restrict__ w0,
                           const float* __restrict__ wmid,
                           const float* __restrict__ wlast){
    const int total = 1800 + 6 * 5625 + 2304;
    for (int idx = blockIdx.x * blockDim.x + threadIdx.x; idx < total; idx += gridDim.x * blockDim.x) {
        int img, off; float v;
        if (idx < 1800) {                       // conv0: [oc][ic(8)][tap]
            const int oc = idx / 72, r = idx % 72, ic = r / 9, tap = r % 9;
            img = 0; off = tap * B_TAP + oc * ROWB + ic * 2;
            v = w0[idx];
        } else if (idx < 1800 + 33750) {        // mid: [L][oc][ic(25)][tap]
            const int j = idx - 1800;
            const int L = j / 5625, jj = j % 5625;
            const int oc = jj / 225, r = jj % 225, ic = r / 9, tap = r % 9;
            img = 1 + L; off = tap * B_TAP + oc * ROWB + ic * 2;
            v = wmid[j];
        } else {                                // last: taps x 8 oc x 32 ic
            const int j = idx - 1800 - 33750;
            const int tap = j / 256, r2 = j % 256, oc = r2 / 32, ic = r2 % 32;
            img = 7; off = tap * B_TAP + oc * ROWB + ic * 2;
            v = (oc < 6 && ic < 25) ? wlast[oc * 225 + ic * 9 + tap] : 0.f;
        }
        __half h, l; split2(v, h, l);
        *(__half*)(g_wimg[img] + off) = h;
        *(__half*)(g_wimg[img] + off + WIMG_HALF) = l;
    }
}

// One layer's MMA. 8 warps; warp owns up to 2 M-tiles (tile = wid + 8*mt).
template<int KT, int NTL>
__device__ __forceinline__ void layer_mma(u32 sb, int lane,
                                          const u32 abase[2], const bool val[2],
                                          float d[2][4][4])
{
    #pragma unroll
    for (int mt = 0; mt < 2; mt++)
        #pragma unroll
        for (int nt = 0; nt < 4; nt++)
            #pragma unroll
            for (int q = 0; q < 4; q++) d[mt][nt][q] = 0.f;

    const int bn  = (lane & 7) + ((lane >> 4) << 3);
    const u32 bko = (u32)(((lane >> 3) & 1) * 16);
    const u32 bbase = (u32)(bn * ROWB) + bko;

    #pragma unroll 1
    for (int tap = 0; tap < 9; tap++) {
        const int dmB = (((tap / 3) * 7 + (tap % 3)) - 8) * 8 * ROWB;
        #pragma unroll
        for (int k = 0; k < KT; k++) {
            const u32 boff = (u32)(tap * B_TAP + k * 32) + bbase;
            u32 bh0[4], bl0[4], bh1[4], bl1[4];
            ldsm4(sb + OFF_BH + boff, bh0);
            ldsm4(sb + OFF_BL + boff, bl0);
            if (NTL > 2) {
                ldsm4(sb + OFF_BH + boff + 1280, bh1);
                ldsm4(sb + OFF_BL + boff + 1280, bl1);
            }
            #pragma unroll
            for (int mt = 0; mt < 2; mt++) {
                if (!val[mt]) continue;
                const u32 aoff = abase[mt] + (u32)(dmB + k * 32);
                u32 ah[4], al[4];
                ldsm4(sb + OFF_AH + aoff, ah);
                ldsm4(sb + OFF_AL + aoff, al);
                hmma(d[mt][0], ah, bh0 + 0);
                if (NTL > 1) hmma(d[mt][1], ah, bh0 + 2);
                if (NTL > 2) { hmma(d[mt][2], ah, bh1 + 0); hmma(d[mt][3], ah, bh1 + 2); }
                hmma(d[mt][0], ah, bl0 + 0);
                if (NTL > 1) hmma(d[mt][1], ah, bl0 + 2);
                if (NTL > 2) { hmma(d[mt][2], ah, bl1 + 0); hmma(d[mt][3], ah, bl1 + 2); }
                hmma(d[mt][0], al, bh0 + 0);
                if (NTL > 1) hmma(d[mt][1], al, bh0 + 2);
                if (NTL > 2) { hmma(d[mt][2], al, bh1 + 0); hmma(d[mt][3], al, bh1 + 2); }
            }
        }
    }
}

__global__ __launch_bounds__(NT, 2)
void Kpcnn_49160195670356_kernel(const float* __restrict__ gin,
                                 const float* __restrict__ b0,
                                 const float* __restrict__ bmid,
                                 const float* __restrict__ blast,
                                 const float* __restrict__ wpost,
                                 const float* __restrict__ bpost,
                                 float* __restrict__ gout)
{
    extern __shared__ char smem[];
    const u32 sb  = smem_u32(smem);
    const int tid = threadIdx.x;
    const int wid = tid >> 5;
    const int lane = tid & 31;
    const long pg = (long)blockIdx.x * PPB;

    float* bias0  = (float*)(smem + OFF_BIAS0);
    float* bias1  = (float*)(smem + OFF_BIAS1);
    float* colors = (float*)(smem + OFF_COL);

    // per-warp tiles: tile = wid + 8*mt, 13 tiles total (paired slots)
    u32 abase[2]; bool val[2]; int sA[2], sB[2], tdup[2];
    #pragma unroll
    for (int mt = 0; mt < 2; mt++) {
        const int tile = wid + mt * 8;
        val[mt] = (tile < 13);
        const int i2 = val[mt] ? 2 * tile : 0;
        const int a_ = (i2 / 5) * 7 + (i2 % 5) + 8;
        const int i3 = (i2 + 1 <= 24) ? (i2 + 1) : 0;
        const int b_ = (i3 / 5) * 7 + (i3 % 5) + 8;
        sA[mt] = a_; sB[mt] = b_;
        tdup[mt] = (i2 + 1 > 24);
        const int ssel = ((lane >> 3) & 1) ? b_ : a_;
        abase[mt] = (u32)((ssel * 8 + (lane & 7)) * ROWB + ((lane >> 4) * 16));
    }

    // ---- zero A region only (B comes from images) ----
    {
        uint4 z = make_uint4(0, 0, 0, 0);
        uint4* p4 = (uint4*)(smem + OFF_AH);
        for (int i = tid; i < (OFF_BH - OFF_AH) / 16; i += NT) p4[i] = z;
    }
    // ---- copy conv0 weight image ----
    {
        const uint4* src = (const uint4*)g_wimg[0];
        uint4* dst = (uint4*)(smem + OFF_BH);
        for (int i = tid; i < WIMG_BYTES / 16; i += NT) dst[i] = src[i];
    }
    __syncthreads();

    // ---- stage input, bias0, colors ----
    for (int i = tid; i < PPB * 200; i += NT) {
        const int p = i / 200, rem = i % 200;
        const int c = rem / 25, pos = rem % 25;
        const int slot = (pos / 5 + 1) * 7 + (pos % 5 + 1);
        const int row = slot * 8 + p;
        const float v = gin[(pg + p) * 200 + rem];
        __half h, l; split2(v, h, l);
        *(__half*)(smem + OFF_AH + row * ROWB + c * 2) = h;
        *(__half*)(smem + OFF_AL + row * ROWB + c * 2) = l;
    }
    if (tid < 32) bias0[tid] = (tid < 25) ? b0[tid] : 0.f;
    if (tid < 144) {
        const int p = tid / 18, j = tid % 18;
        const float* wp = wpost + j * 75;
        const float* ip = gin + (pg + p) * 200;
        float a0 = bpost[j], a1 = 0.f, a2 = 0.f;
        #pragma unroll
        for (int k = 0; k < 25; k++) {
            a0 = fmaf(wp[k],      ip[k],      a0);
            a1 = fmaf(wp[25 + k], ip[25 + k], a1);
            a2 = fmaf(wp[50 + k], ip[50 + k], a2);
        }
        colors[p * 18 + j] = a0 + a1 + a2;
    }
    __syncthreads();

    float d[2][4][4];

    // ---- conv0 (K=16, ic 8..15 zero) ----
    layer_mma<1, 4>(sb, lane, abase, val, d);
    __syncthreads();

    #define EPI_CONV(BIAS) do {                                                   \
        _Pragma("unroll")                                                         \
        for (int mt = 0; mt < 2; mt++) {                                          \
            if (!val[mt]) continue;                                               \
            const int rA = sA[mt] * 8 + (lane >> 2);                              \
            const int rB = sB[mt] * 8 + (lane >> 2);                              \
            _Pragma("unroll")                                                     \
            for (int nt = 0; nt < 4; nt++) {                                      \
                const int col = nt * 8 + (lane & 3) * 2;                          \
                const float b0v = (BIAS)[col], b1v = (BIAS)[col + 1];             \
                float v0 = fmaxf(d[mt][nt][0] + b0v, 0.f);                        \
                float v1 = fmaxf(d[mt][nt][1] + b1v, 0.f);                        \
                __half h0, l0, h1, l1;                                            \
                split2(v0, h0, l0); split2(v1, h1, l1);                           \
                *(u32*)(smem + OFF_AH + rA * ROWB + col * 2) = packh(h0, h1);     \
                *(u32*)(smem + OFF_AL + rA * ROWB + col * 2) = packh(l0, l1);     \
                if (!tdup[mt]) {                                                  \
                    float v2 = fmaxf(d[mt][nt][2] + b0v, 0.f);                    \
                    float v3 = fmaxf(d[mt][nt][3] + b1v, 0.f);                    \
                    __half h2, l2, h3, l3;                                        \
                    split2(v2, h2, l2); split2(v3, h3, l3);                       \
                    *(u32*)(smem + OFF_AH + rB * ROWB + col * 2) = packh(h2, h3); \
                    *(u32*)(smem + OFF_AL + rB * ROWB + col * 2) = packh(l2, l3); \
                }                                                                 \
            }                                                                     \
        }                                                                         \
    } while (0)

    EPI_CONV(bias0);
    {
        const uint4* src = (const uint4*)g_wimg[1];
        uint4* dst = (uint4*)(smem + OFF_BH);
        for (int i = tid; i < WIMG_BYTES / 16; i += NT) dst[i] = src[i];
    }
    if (tid < 32) bias1[tid] = (tid < 25) ? bmid[tid] : 0.f;
    __syncthreads();

    // ---- 6 mid layers ----
    #pragma unroll 1
    for (int L = 0; L < 6; L++) {
        layer_mma<2, 4>(sb, lane, abase, val, d);
        __syncthreads();
        const float* rb = (L & 1) ? bias0 : bias1;
        float* wb = (L & 1) ? bias1 : bias0;
        EPI_CONV(rb);
        {
            const uint4* src = (const uint4*)g_wimg[(L < 5) ? (2 + L) : 7];
            uint4* dst = (uint4*)(smem + OFF_BH);
            for (int i = tid; i < WIMG_BYTES / 16; i += NT) dst[i] = src[i];
        }
        if (L < 5) {
            if (tid < 32) wb[tid] = (tid < 25) ? bmid[(L + 1) * 25 + tid] : 0.f;
        } else {
            if (tid < 8) wb[tid] = (tid < 6) ? blast[tid] : -1e30f;
        }
        __syncthreads();
    }

    // ---- last conv (N=8: 6 logits) + softmax + einsum ----
    layer_mma<2, 1>(sb, lane, abase, val, d);
    __syncthreads();
    const float* lb = bias1;
    #pragma unroll
    for (int mt = 0; mt < 2; mt++) {
        if (!val[mt]) continue;
        const int patch = lane >> 2;
        const int w0i = (lane & 3) * 2;
        const float bw0 = lb[w0i], bw1 = lb[w0i + 1];
        #pragma unroll
        for (int half = 0; half < 2; half++) {
            if (half == 1 && tdup[mt]) continue;
            const float lg0 = d[mt][0][half * 2 + 0] + bw0;
            const float lg1 = d[mt][0][half * 2 + 1] + bw1;
            float mx = fmaxf(lg0, lg1);
            mx = fmaxf(mx, __shfl_xor_sync(0xffffffffu, mx, 1));
            mx = fmaxf(mx, __shfl_xor_sync(0xffffffffu, mx, 2));
            const float e0 = __expf(lg0 - mx);
            const float e1 = __expf(lg1 - mx);
            float sm = e0 + e1;
            sm += __shfl_xor_sync(0xffffffffu, sm, 1);
            sm += __shfl_xor_sync(0xffffffffu, sm, 2);
            const float inv = 1.0f / sm;
            float p0 = 0.f, p1 = 0.f, p2 = 0.f;
            if ((lane & 3) != 3) {
                const float* cl = colors + patch * 18;
                p0 = cl[w0i] * e0      + cl[w0i + 1] * e1;
                p1 = cl[6 + w0i] * e0  + cl[7 + w0i] * e1;
                p2 = cl[12 + w0i] * e0 + cl[13 + w0i] * e1;
            }
            p0 += __shfl_xor_sync(0xffffffffu, p0, 1);
            p0 += __shfl_xor_sync(0xffffffffu, p0, 2);
            p1 += __shfl_xor_sync(0xffffffffu, p1, 1);
            p1 += __shfl_xor_sync(0xffffffffu, p1, 2);
            p2 += __shfl_xor_sync(0xffffffffu, p2, 1);
            p2 += __shfl_xor_sync(0xffffffffu, p2, 2);
            if ((lane & 3) == 0) {
                const int s = half ? sB[mt] : sA[mt];
                const int y = s / 7, x = s % 7;
                const long ob = (pg + patch) * 75 + (y - 1) * 5 + (x - 1);
                gout[ob]      = p0 * inv;
                gout[ob + 25] = p1 * inv;
                gout[ob + 50] = p2 * inv;
            }
        }
    }
}

extern "C" void kernel_launch(void* const* d_in, const int* in_sizes, int n_in,
                              void* d_out, int out_size)
{
    const float* gin   = (const float*)d_in[0];
    const float* w0    = (const float*)d_in[1];
    const float* b0    = (const float*)d_in[2];
    const float* wmid  = (const float*)d_in[3];
    const float* bmid  = (const float*)d_in[4];
    const float* wlast = (const float*)d_in[5];
    const float* blast = (const float*)d_in[6];
    const float* wpost = (const float*)d_in[7];
    const float* bpost = (const float*)d_in[8];
    float* gout = (float*)d_out;

    Kprep_zero<<<90, 256>>>();
    Kprep_fill<<<148, 256>>>(w0, wmid, wlast);

    cudaFuncSetAttribute(Kpcnn_49160195670356_kernel,
                         cudaFuncAttributeMaxDynamicSharedMemorySize, SMEM_TOTAL);

    Kpcnn_49160195670356_kernel<<<32768 / PPB, NT, SMEM_TOTAL>>>(
        gin, b0, bmid, blast, wpost, bpost, gout);
}